// round 14
// baseline (speedup 1.0000x reference)
#include <cuda_runtime.h>
#include <math.h>

// Problem constants (shapes fixed by the dataset)
#define MAXN 50000
#define MAXE 800000
#define MAXT (MAXE + MAXN)

// ---------------- scratch (no cudaMalloc allowed) ----------------
__device__ float g_h1 [MAXN * 256];   // x @ W1            [N, 2*128]
__device__ float g_out1[MAXN * 256];  // elu(conv1)        [N, 256]
__device__ float g_h2 [MAXN * 128];   // out1 @ W2         [N, 128]
__device__ float g_out2[MAXN * 128];  // elu(conv2)        [N, 128]
__device__ float g_h3 [MAXN * 128];   // relu(out2@Wm1+b)  [N, 128]
__device__ float g_as1[MAXN * 2];
__device__ float g_ad1[MAXN * 2];
__device__ float g_as2[MAXN];
__device__ float g_ad2[MAXN];
__device__ int   g_deg   [MAXN];
__device__ int   g_rowptr[MAXN + 1];
__device__ int   g_cursor[MAXN];
__device__ int   g_csr_src[MAXT];

__device__ __forceinline__ float lrelu(float x) { return x > 0.f ? x : 0.2f * x; }
__device__ __forceinline__ float elu(float x)   { return x > 0.f ? x : expm1f(x); }

// ---------------- CSR build (by destination, self-loops appended) ----------------
__global__ void zero_deg_kernel(int n_nodes) {
    int i = blockIdx.x * blockDim.x + threadIdx.x;
    if (i < n_nodes) g_deg[i] = 0;
}

__global__ void degree_kernel(const int* __restrict__ dst, int E, int n_nodes) {
    int i = blockIdx.x * blockDim.x + threadIdx.x;
    int et = E + n_nodes;
    if (i >= et) return;
    int d = (i < E) ? dst[i] : (i - E);
    atomicAdd(&g_deg[d], 1);
}

// single-block exclusive scan over N=50000 degrees; also seeds cursors
__global__ void scan_kernel(int n_nodes) {
    __shared__ int sums[1024];
    int t = threadIdx.x;
    int CH = (n_nodes + 1023) >> 10;
    int b = t * CH;
    int e = min(b + CH, n_nodes);
    int s = 0;
    for (int i = b; i < e; i++) s += g_deg[i];
    sums[t] = s;
    __syncthreads();
    #pragma unroll
    for (int off = 1; off < 1024; off <<= 1) {
        int v = (t >= off) ? sums[t - off] : 0;
        __syncthreads();
        sums[t] += v;
        __syncthreads();
    }
    int excl = (t == 0) ? 0 : sums[t - 1];
    for (int i = b; i < e; i++) {
        int d = g_deg[i];
        g_rowptr[i] = excl;
        g_cursor[i] = excl;
        excl += d;
    }
    if (t == 1023) g_rowptr[n_nodes] = sums[1023];
}

__global__ void scatter_kernel(const int* __restrict__ src, const int* __restrict__ dst,
                               int E, int n_nodes) {
    int i = blockIdx.x * blockDim.x + threadIdx.x;
    int et = E + n_nodes;
    if (i >= et) return;
    int s, d;
    if (i < E) { s = src[i]; d = dst[i]; }
    else       { s = d = i - E; }
    int pos = atomicAdd(&g_cursor[d], 1);
    g_csr_src[pos] = s;
}

// ---------------- SGEMM: C[M,N] = A[M,K] @ B[K,N] (+bias)(+relu) ----------------
// BM=BN=64, BK=16, 256 threads, 4x4 microtile. Requires N%64==0, K%16==0.
__global__ __launch_bounds__(256)
void sgemm64(const float* __restrict__ A, const float* __restrict__ B,
             float* __restrict__ C, int M, int N, int K,
             const float* __restrict__ bias, int do_relu) {
    __shared__ float As[16 * 64];
    __shared__ float Bs[16 * 64];
    int tid = threadIdx.x;
    int tx = tid & 15;        // N microtile index
    int ty = tid >> 4;        // M microtile index
    int m0 = blockIdx.x * 64;
    int n0 = blockIdx.y * 64;

    int ar = tid >> 2;            // 0..63 row within A tile
    int ac = (tid & 3) * 4;       // 0,4,8,12 col group
    int br = tid >> 4;            // 0..15 row within B tile
    int bc = (tid & 15) * 4;      // 0..60 col group

    float acc[4][4];
    #pragma unroll
    for (int i = 0; i < 4; i++)
        #pragma unroll
        for (int j = 0; j < 4; j++) acc[i][j] = 0.f;

    for (int k0 = 0; k0 < K; k0 += 16) {
        float4 a = make_float4(0.f, 0.f, 0.f, 0.f);
        int gm = m0 + ar;
        if (gm < M) a = *(const float4*)(A + (size_t)gm * K + k0 + ac);
        As[(ac + 0) * 64 + ar] = a.x;
        As[(ac + 1) * 64 + ar] = a.y;
        As[(ac + 2) * 64 + ar] = a.z;
        As[(ac + 3) * 64 + ar] = a.w;
        float4 bv = *(const float4*)(B + (size_t)(k0 + br) * N + n0 + bc);
        *(float4*)(Bs + br * 64 + bc) = bv;
        __syncthreads();
        #pragma unroll
        for (int k = 0; k < 16; k++) {
            float4 av = *(const float4*)(As + k * 64 + ty * 4);
            float4 bb = *(const float4*)(Bs + k * 64 + tx * 4);
            float aa[4] = {av.x, av.y, av.z, av.w};
            float bbv[4] = {bb.x, bb.y, bb.z, bb.w};
            #pragma unroll
            for (int i = 0; i < 4; i++)
                #pragma unroll
                for (int j = 0; j < 4; j++)
                    acc[i][j] = fmaf(aa[i], bbv[j], acc[i][j]);
        }
        __syncthreads();
    }

    int col = n0 + tx * 4;
    float b4[4] = {0.f, 0.f, 0.f, 0.f};
    if (bias) { b4[0] = bias[col]; b4[1] = bias[col+1]; b4[2] = bias[col+2]; b4[3] = bias[col+3]; }
    #pragma unroll
    for (int i = 0; i < 4; i++) {
        int row = m0 + ty * 4 + i;
        if (row < M) {
            float4 o;
            o.x = acc[i][0] + b4[0];
            o.y = acc[i][1] + b4[1];
            o.z = acc[i][2] + b4[2];
            o.w = acc[i][3] + b4[3];
            if (do_relu) {
                o.x = fmaxf(o.x, 0.f); o.y = fmaxf(o.y, 0.f);
                o.z = fmaxf(o.z, 0.f); o.w = fmaxf(o.w, 0.f);
            }
            *(float4*)(C + (size_t)row * N + col) = o;
        }
    }
}

// ---------------- attention coefficients: warp per (node, head) ----------------
__global__ void alpha_kernel(const float* __restrict__ h,
                             const float* __restrict__ att_src,
                             const float* __restrict__ att_dst,
                             float* __restrict__ as_, float* __restrict__ ad_,
                             int n_nodes, int heads) {
    int gw = (blockIdx.x * blockDim.x + threadIdx.x) >> 5;
    int lane = threadIdx.x & 31;
    int total = n_nodes * heads;
    if (gw >= total) return;
    int n = gw / heads;
    int hd = gw - n * heads;
    const float4* hp = (const float4*)(h + (size_t)n * heads * 128 + hd * 128) + lane;
    float4 v = *hp;
    float4 s4 = *((const float4*)(att_src + hd * 128) + lane);
    float4 d4 = *((const float4*)(att_dst + hd * 128) + lane);
    float ss = v.x * s4.x + v.y * s4.y + v.z * s4.z + v.w * s4.w;
    float dd = v.x * d4.x + v.y * d4.y + v.z * d4.z + v.w * d4.w;
    #pragma unroll
    for (int o = 16; o; o >>= 1) {
        ss += __shfl_xor_sync(0xffffffffu, ss, o);
        dd += __shfl_xor_sync(0xffffffffu, dd, o);
    }
    if (lane == 0) { as_[n * heads + hd] = ss; ad_[n * heads + hd] = dd; }
}

// ---------------- conv1 softmax-aggregate: warp per dst node (2 heads, 256 feats) ----------------
__global__ __launch_bounds__(256)
void gat_agg1(const float* __restrict__ h1,
              const float* __restrict__ as1, const float* __restrict__ ad1,
              const float* __restrict__ b1,
              float* __restrict__ out1, int n_nodes) {
    int n = (blockIdx.x * blockDim.x + threadIdx.x) >> 5;
    int lane = threadIdx.x & 31;
    if (n >= n_nodes) return;
    int start = g_rowptr[n], end = g_rowptr[n + 1];
    float ad0 = ad1[2 * n], ad1v = ad1[2 * n + 1];

    float m0 = -1e30f, m1 = -1e30f;
    for (int j = start + lane; j < end; j += 32) {
        int s = g_csr_src[j];
        float2 a = *(const float2*)(as1 + 2 * s);
        m0 = fmaxf(m0, lrelu(a.x + ad0));
        m1 = fmaxf(m1, lrelu(a.y + ad1v));
    }
    #pragma unroll
    for (int o = 16; o; o >>= 1) {
        m0 = fmaxf(m0, __shfl_xor_sync(0xffffffffu, m0, o));
        m1 = fmaxf(m1, __shfl_xor_sync(0xffffffffu, m1, o));
    }

    float d0 = 0.f, d1 = 0.f;
    float acc[8] = {0.f, 0.f, 0.f, 0.f, 0.f, 0.f, 0.f, 0.f};
    for (int j = start; j < end; j++) {
        int s = g_csr_src[j];
        float2 a = *(const float2*)(as1 + 2 * s);
        float x0 = __expf(lrelu(a.x + ad0) - m0);
        float x1 = __expf(lrelu(a.y + ad1v) - m1);
        d0 += x0; d1 += x1;
        float ex = (lane < 16) ? x0 : x1;
        const float4* hp = (const float4*)(h1 + (size_t)s * 256) + lane * 2;
        float4 v0 = hp[0], v1 = hp[1];
        acc[0] += ex * v0.x; acc[1] += ex * v0.y; acc[2] += ex * v0.z; acc[3] += ex * v0.w;
        acc[4] += ex * v1.x; acc[5] += ex * v1.y; acc[6] += ex * v1.z; acc[7] += ex * v1.w;
    }
    float dm = (lane < 16) ? d0 : d1;
    float w = 1.f / fmaxf(dm, 1e-16f);
    int off = n * 256 + lane * 8;
    #pragma unroll
    for (int i = 0; i < 8; i++) {
        float v = acc[i] * w + b1[lane * 8 + i];
        out1[off + i] = elu(v);
    }
}

// ---------------- conv2 softmax-aggregate: warp per dst node (1 head, 128 feats) ----------------
__global__ __launch_bounds__(256)
void gat_agg2(const float* __restrict__ h2,
              const float* __restrict__ as2, const float* __restrict__ ad2,
              const float* __restrict__ b2,
              float* __restrict__ out2, int n_nodes) {
    int n = (blockIdx.x * blockDim.x + threadIdx.x) >> 5;
    int lane = threadIdx.x & 31;
    if (n >= n_nodes) return;
    int start = g_rowptr[n], end = g_rowptr[n + 1];
    float adn = ad2[n];

    float m = -1e30f;
    for (int j = start + lane; j < end; j += 32) {
        int s = g_csr_src[j];
        m = fmaxf(m, lrelu(as2[s] + adn));
    }
    #pragma unroll
    for (int o = 16; o; o >>= 1)
        m = fmaxf(m, __shfl_xor_sync(0xffffffffu, m, o));

    float d = 0.f;
    float acc[4] = {0.f, 0.f, 0.f, 0.f};
    for (int j = start; j < end; j++) {
        int s = g_csr_src[j];
        float ex = __expf(lrelu(as2[s] + adn) - m);
        d += ex;
        float4 v = *((const float4*)(h2 + (size_t)s * 128) + lane);
        acc[0] += ex * v.x; acc[1] += ex * v.y; acc[2] += ex * v.z; acc[3] += ex * v.w;
    }
    float w = 1.f / fmaxf(d, 1e-16f);
    int off = n * 128 + lane * 4;
    #pragma unroll
    for (int i = 0; i < 4; i++) {
        float v = acc[i] * w + b2[lane * 4 + i];
        out2[off + i] = elu(v);
    }
}

// ---------------- final layer: out[N,8] = relu(h3 @ Wm2 + bm2) ----------------
__global__ __launch_bounds__(256)
void mlp2_kernel(const float* __restrict__ h3, const float* __restrict__ Wm2,
                 const float* __restrict__ bm2, float* __restrict__ out, int n_nodes) {
    __shared__ float sW[128 * 8];
    __shared__ float sb[8];
    int tid = threadIdx.x;
    for (int i = tid; i < 1024; i += 256) sW[i] = Wm2[i];
    if (tid < 8) sb[tid] = bm2[tid];
    __syncthreads();
    int n = blockIdx.x * 32 + (tid >> 3);
    int c = tid & 7;
    if (n >= n_nodes) return;
    const float4* hp = (const float4*)(h3 + (size_t)n * 128);
    float s = 0.f;
    #pragma unroll
    for (int k4 = 0; k4 < 32; k4++) {
        float4 v = hp[k4];
        s += v.x * sW[(k4 * 4 + 0) * 8 + c];
        s += v.y * sW[(k4 * 4 + 1) * 8 + c];
        s += v.z * sW[(k4 * 4 + 2) * 8 + c];
        s += v.w * sW[(k4 * 4 + 3) * 8 + c];
    }
    out[n * 8 + c] = fmaxf(s + sb[c], 0.f);
}

// ---------------- launch ----------------
extern "C" void kernel_launch(void* const* d_in, const int* in_sizes, int n_in,
                              void* d_out, int out_size) {
    const float* x    = (const float*)d_in[0];
    const int*   ei   = (const int*)d_in[1];
    const float* W1   = (const float*)d_in[2];
    const float* a1s  = (const float*)d_in[3];
    const float* a1d  = (const float*)d_in[4];
    const float* b1   = (const float*)d_in[5];
    const float* W2   = (const float*)d_in[6];
    const float* a2s  = (const float*)d_in[7];
    const float* a2d  = (const float*)d_in[8];
    const float* b2   = (const float*)d_in[9];
    const float* Wm1  = (const float*)d_in[10];
    const float* bm1  = (const float*)d_in[11];
    const float* Wm2  = (const float*)d_in[12];
    const float* bm2  = (const float*)d_in[13];
    float* out = (float*)d_out;

    int n = in_sizes[0] / 128;       // 50000
    int e = in_sizes[1] / 2;         // 800000
    int et = e + n;                  // self loops appended
    const int* esrc = ei;
    const int* edst = ei + e;

    float *h1, *o1, *h2, *o2, *h3, *as1p, *ad1p, *as2p, *ad2p;
    cudaGetSymbolAddress((void**)&h1,  g_h1);
    cudaGetSymbolAddress((void**)&o1,  g_out1);
    cudaGetSymbolAddress((void**)&h2,  g_h2);
    cudaGetSymbolAddress((void**)&o2,  g_out2);
    cudaGetSymbolAddress((void**)&h3,  g_h3);
    cudaGetSymbolAddress((void**)&as1p, g_as1);
    cudaGetSymbolAddress((void**)&ad1p, g_ad1);
    cudaGetSymbolAddress((void**)&as2p, g_as2);
    cudaGetSymbolAddress((void**)&ad2p, g_ad2);

    // CSR by destination (shared by both conv layers)
    zero_deg_kernel<<<(n + 255) / 256, 256>>>(n);
    degree_kernel<<<(et + 255) / 256, 256>>>(edst, e, n);
    scan_kernel<<<1, 1024>>>(n);
    scatter_kernel<<<(et + 255) / 256, 256>>>(esrc, edst, e, n);

    // conv1
    sgemm64<<<dim3((n + 63) / 64, 256 / 64), 256>>>(x, W1, h1, n, 256, 128, nullptr, 0);
    {
        int total = n * 2;
        alpha_kernel<<<(total * 32 + 255) / 256, 256>>>(h1, a1s, a1d, as1p, ad1p, n, 2);
    }
    gat_agg1<<<(n + 7) / 8, 256>>>(h1, as1p, ad1p, b1, o1, n);

    // conv2
    sgemm64<<<dim3((n + 63) / 64, 128 / 64), 256>>>(o1, W2, h2, n, 128, 256, nullptr, 0);
    alpha_kernel<<<(n * 32 + 255) / 256, 256>>>(h2, a2s, a2d, as2p, ad2p, n, 1);
    gat_agg2<<<(n + 7) / 8, 256>>>(h2, as2p, ad2p, b2, o2, n);

    // MLP head
    sgemm64<<<dim3((n + 63) / 64, 128 / 64), 256>>>(o2, Wm1, h3, n, 128, 128, bm1, 1);
    mlp2_kernel<<<(n + 31) / 32, 256>>>(h3, Wm2, bm2, out, n);
}